// round 16
// baseline (speedup 1.0000x reference)
#include <cuda_runtime.h>
#include <cuda_bf16.h>
#include <math.h>
#include <stdint.h>

#define D_MODEL 1024
#define NHEAD   16
#define DH      64
#define NLAYER  6
#define DIM_FF  4096
#define BATCH   8
#define SEQ     1024
#define M_ROWS  (BATCH*SEQ)   // 8192
#define DSTRIDE ((size_t)M_ROWS * D_MODEL)

// ---------------- scratch ----------------
__device__ float g_tmp [4 * M_ROWS * D_MODEL];
__device__ float g_cls [BATCH * D_MODEL];
__device__ unsigned char g_kpm[M_ROWS];

__device__ __nv_bfloat16 g_wh[75497472];
__device__ __nv_bfloat16 g_wl[75497472];
__device__ __nv_bfloat16 g_xh[M_ROWS * D_MODEL];
__device__ __nv_bfloat16 g_xl[M_ROWS * D_MODEL];
__device__ __nv_bfloat16 g_ah[M_ROWS * D_MODEL];
__device__ __nv_bfloat16 g_al[M_ROWS * D_MODEL];
__device__ __nv_bfloat16 g_fh[M_ROWS * DIM_FF];
__device__ __nv_bfloat16 g_fl[M_ROWS * DIM_FF];
__device__ __nv_bfloat16 g_qh[M_ROWS * D_MODEL];
__device__ __nv_bfloat16 g_ql[M_ROWS * D_MODEL];
__device__ __nv_bfloat16 g_kh[M_ROWS * D_MODEL];
__device__ __nv_bfloat16 g_kl[M_ROWS * D_MODEL];
__device__ __nv_bfloat16 g_vh[M_ROWS * D_MODEL];   // [b,h,l,dh]
__device__ __nv_bfloat16 g_vl[M_ROWS * D_MODEL];

// ---------------- helpers ----------------
__device__ __forceinline__ uint32_t smem_u32(const void* p) {
    uint32_t a;
    asm("{ .reg .u64 t; cvta.to.shared.u64 t, %1; cvt.u32.u64 %0, t; }"
        : "=r"(a) : "l"(p));
    return a;
}

#define CPA16(dst, src) \
    asm volatile("cp.async.cg.shared.global [%0], [%1], 16;" \
                 :: "r"(dst), "l"(src) : "memory")
#define CPA_COMMIT() asm volatile("cp.async.commit_group;" ::: "memory")
#define CPA_WAIT1()  asm volatile("cp.async.wait_group 1;" ::: "memory")
#define CPA_WAIT0()  asm volatile("cp.async.wait_group 0;" ::: "memory")

#define LDSM4(r, addr) \
    asm volatile("ldmatrix.sync.aligned.m8n8.x4.shared.b16 {%0,%1,%2,%3}, [%4];" \
                 : "=r"((r)[0]), "=r"((r)[1]), "=r"((r)[2]), "=r"((r)[3]) \
                 : "r"(addr))

#define LDSM4T(r, addr) \
    asm volatile("ldmatrix.sync.aligned.m8n8.x4.trans.shared.b16 {%0,%1,%2,%3}, [%4];" \
                 : "=r"((r)[0]), "=r"((r)[1]), "=r"((r)[2]), "=r"((r)[3]) \
                 : "r"(addr))

__device__ __forceinline__ void mma16816(float* d, const uint32_t* a, const uint32_t* b) {
    asm volatile(
        "mma.sync.aligned.m16n8k16.row.col.f32.bf16.bf16.f32 "
        "{%0,%1,%2,%3}, {%4,%5,%6,%7}, {%8,%9}, {%0,%1,%2,%3};"
        : "+f"(d[0]), "+f"(d[1]), "+f"(d[2]), "+f"(d[3])
        : "r"(a[0]), "r"(a[1]), "r"(a[2]), "r"(a[3]), "r"(b[0]), "r"(b[1]));
}

__device__ __forceinline__ void split2(float v0, float v1,
                                       uint32_t& hp, uint32_t& lp) {
    uint32_t u0 = __float_as_uint(v0), u1 = __float_as_uint(v1);
    asm("prmt.b32 %0, %1, %2, 0x7632;" : "=r"(hp) : "r"(u0), "r"(u1));
    float h0 = __uint_as_float(u0 & 0xffff0000u);
    float h1 = __uint_as_float(u1 & 0xffff0000u);
    float l0 = v0 - h0, l1 = v1 - h1;
    asm("cvt.rn.bf16x2.f32 %0, %1, %2;" : "=r"(lp) : "f"(l1), "f"(l0));
}

__device__ __forceinline__ float2 bf2f2(uint32_t u) {
    __nv_bfloat162 h = *(__nv_bfloat162*)&u;
    float2 r;
    r.x = __bfloat162float(h.x);
    r.y = __bfloat162float(h.y);
    return r;
}

// ---------------- embedding (+mask fused) ----------------
__global__ void embed_kernel(const int* __restrict__ ids,
                             const float* __restrict__ tok,
                             const float* __restrict__ pos) {
    int idx4 = blockIdx.x * blockDim.x + threadIdx.x;
    int base = idx4 << 2;
    int bl   = base >> 10;
    int d    = base & 1023;
    int t    = ids[bl];
    if (d == 0)
        g_kpm[bl] = (t == 0 && (bl & (SEQ - 1)) != 0) ? 1 : 0;
    float4 tv = *(const float4*)(tok + (size_t)t * D_MODEL + d);
    float4 pv = *(const float4*)(pos + (size_t)(bl & (SEQ - 1)) * D_MODEL + d);
    float4 o;
    o.x = tv.x + pv.x; o.y = tv.y + pv.y; o.z = tv.z + pv.z; o.w = tv.w + pv.w;
    uint2 hp, lp;
    split2(o.x, o.y, hp.x, lp.x);
    split2(o.z, o.w, hp.y, lp.y);
    *(uint2*)(g_xh + base) = hp;
    *(uint2*)(g_xl + base) = lp;
}

// ---------------- weight fp32 -> bf16 hi/lo (16 elems/thread) ---------------
__global__ void cvt_kernel(const float* __restrict__ s,
                           __nv_bfloat16* __restrict__ h,
                           __nv_bfloat16* __restrict__ l, int n16) {
    int i = blockIdx.x * blockDim.x + threadIdx.x;
    if (i >= n16) return;
#pragma unroll
    for (int p = 0; p < 2; ++p) {
        int j = 2 * i + p;
        float4 v0 = ((const float4*)s)[2 * j];
        float4 v1 = ((const float4*)s)[2 * j + 1];
        uint4 hv, lv;
        split2(v0.x, v0.y, hv.x, lv.x);
        split2(v0.z, v0.w, hv.y, lv.y);
        split2(v1.x, v1.y, hv.z, lv.z);
        split2(v1.z, v1.w, hv.w, lv.w);
        ((uint4*)h)[j] = hv;
        ((uint4*)l)[j] = lv;
    }
}

// ---------------- mma GEMM: C = A @ B^T + bias -------------------------------
// Template MI: 4 -> 256-row CTA tile (R7 config), 2 -> 128-row CTA tile.
// Warp grid 4(M) x 2(N); warp M-tile = 16*MI. BK=32, 3-stage, prefetch-dist-2.
#define ROWB   80
#define BTILE  (128 * ROWB)

template <int MODE, int SPLITK, int MI>
__global__ void __launch_bounds__(256, 1)
gemm_mma(const __nv_bfloat16* __restrict__ Ah, const __nv_bfloat16* __restrict__ Al,
         const __nv_bfloat16* __restrict__ Bh, const __nv_bfloat16* __restrict__ Bl,
         const float* __restrict__ bias,
         float* __restrict__ Cf,
         __nv_bfloat16* __restrict__ Ch, __nv_bfloat16* __restrict__ Cl,
         int K, int Ntot)
{
    constexpr int AT   = MI * 64 * ROWB;
    constexpr int STGv = 2 * AT + 2 * BTILE;

    extern __shared__ char sm8[];
    uint32_t sb = smem_u32(sm8);
    int tid = threadIdx.x, wid = tid >> 5, lane = tid & 31;
    int m0 = blockIdx.y * (MI * 64), n0 = blockIdx.x << 7;
    int kz = (SPLITK > 1) ? blockIdx.z : 0;
    int Keff = K / SPLITK;
    long kofs = (long)kz * Keff;
    int wm = wid & 3, wn = wid >> 2;
    int g = lane >> 2, q = lane & 3;

    float acc[MI][8][4];
#pragma unroll
    for (int mi = 0; mi < MI; ++mi)
#pragma unroll
        for (int ni = 0; ni < 8; ++ni)
#pragma unroll
            for (int r = 0; r < 4; ++r) acc[mi][ni][r] = 0.f;

    int NC = Keff >> 5;

    auto load_stage = [&](int s, int c) {
        uint32_t st = sb + (uint32_t)s * STGv;
        long kb = kofs + ((long)c << 5);
#pragma unroll
        for (int it = 0; it < MI; ++it) {
            int idx = it * 256 + tid;
            int r = idx >> 2, ch = idx & 3;
            uint32_t so = (uint32_t)r * ROWB + ch * 16;
            CPA16(st + so,      Ah + (size_t)(m0 + r) * K + kb + ch * 8);
            CPA16(st + AT + so, Al + (size_t)(m0 + r) * K + kb + ch * 8);
        }
#pragma unroll
        for (int it = 0; it < 2; ++it) {
            int idx = it * 256 + tid;
            int r = idx >> 2, ch = idx & 3;
            uint32_t so = (uint32_t)r * ROWB + ch * 16;
            CPA16(st + 2 * AT + so,         Bh + (size_t)(n0 + r) * K + kb + ch * 8);
            CPA16(st + 2 * AT + BTILE + so, Bl + (size_t)(n0 + r) * K + kb + ch * 8);
        }
    };

    uint32_t arow = (uint32_t)(wm * (16 * MI) + (lane & 15)) * ROWB + (lane >> 4) * 16;
    uint32_t brow = (uint32_t)(wn * 64 + ((lane >> 4) << 3) + (lane & 7)) * ROWB
                  + ((lane >> 3) & 1) * 16;

    load_stage(0, 0); CPA_COMMIT();
    load_stage(1, 1); CPA_COMMIT();

    int s = 0;
    for (int c = 0; c < NC; ++c) {
        if (c + 1 < NC) { CPA_WAIT1(); } else { CPA_WAIT0(); }
        __syncthreads();

        uint32_t base = sb + (uint32_t)s * STGv;
        uint32_t aHb = base + arow, aLb = aHb + AT;
        uint32_t bHb = base + 2 * AT + brow, bLb = bHb + BTILE;

#pragma unroll
        for (int ks = 0; ks < 2; ++ks) {
            uint32_t ko = ks * 32;
            uint32_t ah[MI][4], al[MI][4];
#pragma unroll
            for (int mi = 0; mi < MI; ++mi) {
                LDSM4(ah[mi], aHb + mi * (16 * ROWB) + ko);
                LDSM4(al[mi], aLb + mi * (16 * ROWB) + ko);
            }
#pragma unroll
            for (int nj2 = 0; nj2 < 4; ++nj2) {
                uint32_t bh4[4], bl4[4];
                LDSM4(bh4, bHb + nj2 * (16 * ROWB) + ko);
                LDSM4(bl4, bLb + nj2 * (16 * ROWB) + ko);
#pragma unroll
                for (int half = 0; half < 2; ++half) {
                    int ni = nj2 * 2 + half;
                    uint32_t bhh[2] = {bh4[half * 2], bh4[half * 2 + 1]};
#pragma unroll
                    for (int mi = 0; mi < MI; ++mi)
                        mma16816(acc[mi][ni], ah[mi], bhh);
                }
#pragma unroll
                for (int half = 0; half < 2; ++half) {
                    int ni = nj2 * 2 + half;
                    uint32_t bll[2] = {bl4[half * 2], bl4[half * 2 + 1]};
#pragma unroll
                    for (int mi = 0; mi < MI; ++mi)
                        mma16816(acc[mi][ni], ah[mi], bll);
                }
#pragma unroll
                for (int half = 0; half < 2; ++half) {
                    int ni = nj2 * 2 + half;
                    uint32_t bhh[2] = {bh4[half * 2], bh4[half * 2 + 1]};
#pragma unroll
                    for (int mi = 0; mi < MI; ++mi)
                        mma16816(acc[mi][ni], al[mi], bhh);
                }
            }
        }

        if (c + 2 < NC) {
            int ws = s + 2; if (ws >= 3) ws -= 3;
            load_stage(ws, c + 2);
            CPA_COMMIT();
        }
        if (++s == 3) s = 0;
    }

    // ---- epilogue ----
    float* Cfz = Cf + (size_t)kz * M_ROWS * Ntot;
    float bscale = (SPLITK > 1 && kz != 0) ? 0.f : 1.f;
#pragma unroll
    for (int mi = 0; mi < MI; ++mi) {
#pragma unroll
        for (int ni = 0; ni < 8; ++ni) {
            int col = n0 + wn * 64 + ni * 8 + q * 2;
            float2 bv = *(const float2*)(bias + col);
            float* a = acc[mi][ni];
#pragma unroll
            for (int half = 0; half < 2; ++half) {
                int row = m0 + wm * (16 * MI) + mi * 16 + g + half * 8;
                float v0 = a[half * 2 + 0] + bv.x * bscale;
                float v1 = a[half * 2 + 1] + bv.y * bscale;
                if (MODE == 0) {
                    float2 o; o.x = v0; o.y = v1;
                    *(float2*)(Cfz + (size_t)row * Ntot + col) = o;
                } else if (MODE == 1) {
                    v0 = 0.5f * v0 * (1.0f + erff(v0 * 0.70710678118654752f));
                    v1 = 0.5f * v1 * (1.0f + erff(v1 * 0.70710678118654752f));
                    uint32_t hp, lp;
                    split2(v0, v1, hp, lp);
                    size_t off = (size_t)row * Ntot + col;
                    *(uint32_t*)(Ch + off) = hp;
                    *(uint32_t*)(Cl + off) = lp;
                } else {
                    int bb = row >> 10, l = row & 1023;
                    int cat = col >> 10, cc = col & 1023;
                    int hh = cc >> 6, d = cc & 63;
                    if (cat == 0) { v0 *= 0.125f; v1 *= 0.125f; }
                    uint32_t hp, lp;
                    split2(v0, v1, hp, lp);
                    size_t base2 = (((size_t)bb * NHEAD + hh) * SEQ + l) * DH + d;
                    if (cat == 0) {
                        *(uint32_t*)(g_qh + base2) = hp;
                        *(uint32_t*)(g_ql + base2) = lp;
                    } else if (cat == 1) {
                        *(uint32_t*)(g_kh + base2) = hp;
                        *(uint32_t*)(g_kl + base2) = lp;
                    } else {
                        *(uint32_t*)(g_vh + base2) = hp;
                        *(uint32_t*)(g_vl + base2) = lp;
                    }
                }
            }
        }
    }
}

#define GS_MI4 (3 * (2 * (256 * ROWB) + 2 * BTILE))   // 184320
#define GS_MI2 (3 * (2 * (128 * ROWB) + 2 * BTILE))   // 122880

// ---------------- flash attention (R13 config) -------------------------------
#define AT_STR   144
#define AT_QB    (128 * AT_STR)
#define AT_KVST  (4 * 64 * AT_STR)
#define AT_SMEM  (2 * AT_QB + 3 * AT_KVST + 3 * 64 * 4)
#define NKT      (SEQ / 64)

__global__ void __launch_bounds__(256, 1)
attn_tc() {
    extern __shared__ char sma[];
    uint32_t sb = smem_u32(sma);
    int tid = threadIdx.x, wid = tid >> 5, lane = tid & 31;
    int g = lane >> 2, q = lane & 3;
    int q0 = blockIdx.x << 7;
    int h  = blockIdx.y;
    int b  = blockIdx.z;
    size_t bh = (size_t)b * NHEAD + h;

    const __nv_bfloat16* qhp = g_qh + bh * SEQ * DH;
    const __nv_bfloat16* qlp = g_ql + bh * SEQ * DH;
    const __nv_bfloat16* khp = g_kh + bh * SEQ * DH;
    const __nv_bfloat16* klp = g_kl + bh * SEQ * DH;
    const __nv_bfloat16* vhp = g_vh + bh * SEQ * DH;
    const __nv_bfloat16* vlp = g_vl + bh * SEQ * DH;

    uint32_t sQh = sb, sQl = sb + AT_QB;
    uint32_t sKV0 = sb + 2 * AT_QB;
    float* msks = (float*)(sma + 2 * AT_QB + 3 * AT_KVST);

#pragma unroll
    for (int it = 0; it < 4; ++it) {
        int idx = it * 256 + tid;
        int r = idx >> 3, ch = idx & 7;
        uint32_t dst = (uint32_t)r * AT_STR + ch * 16;
        CPA16(sQh + dst, qhp + (size_t)(q0 + r) * DH + ch * 8);
        CPA16(sQl + dst, qlp + (size_t)(q0 + r) * DH + ch * 8);
    }

    auto load_kv = [&](int s, int t) {
        uint32_t st = sKV0 + (uint32_t)s * AT_KVST;
#pragma unroll
        for (int it = 0; it < 2; ++it) {
            int idx = it * 256 + tid;
            int r = idx >> 3, ch = idx & 7;
            uint32_t dst = (uint32_t)r * AT_STR + ch * 16;
            size_t go = (size_t)(t * 64 + r) * DH + ch * 8;
            CPA16(st + dst,         khp + go);
            CPA16(st + 9216 + dst,  klp + go);
            CPA16(st + 18432 + dst, vhp + go);
            CPA16(st + 27648 + dst, vlp + go);
        }
        if (tid < 64)
            msks[s * 64 + tid] = g_kpm[b * SEQ + t * 64 + tid] ? 0.f : 1.f;
    };

    load_kv(0, 0); CPA_COMMIT();
    load_kv(1, 1); CPA_COMMIT();

    uint32_t qrow = (uint32_t)(wid * 16 + (lane & 15)) * AT_STR + (lane >> 4) * 16;
    uint32_t brow = (uint32_t)(((lane >> 4) << 3) + (lane & 7)) * AT_STR
                  + ((lane >> 3) & 1) * 16;
    uint32_t vtrow = (uint32_t)((lane & 7) + ((lane >> 3) & 1) * 8) * AT_STR
                   + (lane >> 4) * 16;

    uint32_t qfh[4][4], qfl[4][4];
    float cO[8][4];
#pragma unroll
    for (int j = 0; j < 8; ++j)
#pragma unroll
        for (int r = 0; r < 4; ++r) cO[j][r] = 0.f;
    float m0 = -1e30f, m1 = -1e30f, l0 = 0.f, l1 = 0.f;

    int s = 0;
    for (int t = 0; t < NKT; ++t) {
        if (t + 1 < NKT) { CPA_WAIT1(); } else { CPA_WAIT0(); }
        __syncthreads();
        if (t + 2 < NKT) {
            int ws = s + 2; if (ws >= 3) ws -= 3;
            load_kv(ws, t + 2);
            CPA_COMMIT();
        }

        if (t == 0) {
#pragma unroll
            for (int ks = 0; ks < 4; ++ks) {
                LDSM4(qfh[ks], sQh + qrow + ks * 32);
                LDSM4(qfl[ks], sQl + qrow + ks * 32);
            }
        }

        uint32_t kb = sKV0 + (uint32_t)s * AT_KVST;

        float cS[8][4];
#pragma unroll
        for (int j = 0; j < 8; ++j)
#pragma unroll
            for (int r = 0; r < 4; ++r) cS[j][r] = 0.f;

#pragma unroll
        for (int ks = 0; ks < 4; ++ks) {
            uint32_t ko = ks * 32;
#pragma unroll
            for (int nj2 = 0; nj2 < 4; ++nj2) {
                uint32_t kh4[4], kl4[4];
                LDSM4(kh4, kb + brow + nj2 * (16 * AT_STR) + ko);
                LDSM4(kl4, kb + 9216 + brow + nj2 * (16 * AT_STR) + ko);
#pragma unroll
                for (int half = 0; half < 2; ++half) {
                    int j = nj2 * 2 + half;
                    uint32_t bhh[2] = {kh4[half * 2], kh4[half * 2 + 1]};
                    mma16816(cS[j], qfh[ks], bhh);
                }
#pragma unroll
                for (int half = 0; half < 2; ++half) {
                    int j = nj2 * 2 + half;
                    uint32_t bll[2] = {kl4[half * 2], kl4[half * 2 + 1]};
                    mma16816(cS[j], qfh[ks], bll);
                }
#pragma unroll
                for (int half = 0; half < 2; ++half) {
                    int j = nj2 * 2 + half;
                    uint32_t bhh[2] = {kh4[half * 2], kh4[half * 2 + 1]};
                    mma16816(cS[j], qfl[ks], bhh);
                }
            }
        }

        float lm0 = -1e30f, lm1 = -1e30f;
#pragma unroll
        for (int j = 0; j < 8; ++j) {
            lm0 = fmaxf(lm0, fmaxf(cS[j][0], cS[j][1]));
            lm1 = fmaxf(lm1, fmaxf(cS[j][2], cS[j][3]));
        }
        lm0 = fmaxf(lm0, __shfl_xor_sync(0xffffffffu, lm0, 1));
        lm0 = fmaxf(lm0, __shfl_xor_sync(0xffffffffu, lm0, 2));
        lm1 = fmaxf(lm1, __shfl_xor_sync(0xffffffffu, lm1, 1));
        lm1 = fmaxf(lm1, __shfl_xor_sync(0xffffffffu, lm1, 2));
        float mn0 = fmaxf(m0, lm0), mn1 = fmaxf(m1, lm1);
        float a0 = __expf(m0 - mn0), a1 = __expf(m1 - mn1);

        uint32_t PH[8][2], PL[8][2];
        float s0 = 0.f, s1 = 0.f;
#pragma unroll
        for (int j = 0; j < 8; ++j) {
            float mmA = msks[s * 64 + 8 * j + 2 * q];
            float mmB = msks[s * 64 + 8 * j + 2 * q + 1];
            float p0 = __expf(cS[j][0] - mn0) * mmA;
            float p1 = __expf(cS[j][1] - mn0) * mmB;
            float p2 = __expf(cS[j][2] - mn1) * mmA;
            float p3 = __expf(cS[j][3] - mn1) * mmB;
            s0 += p0 + p1; s1 += p2 + p3;
            split2(p0, p1, PH[j][0], PL[j][0]);
            split2(p2, p3, PH[j][1], PL[j][1]);
        }
        s0 += __shfl_xor_sync(0xffffffffu, s0, 1);
        s0 += __shfl_xor_sync(0xffffffffu, s0, 2);
        s1 += __shfl_xor_sync(0xffffffffu, s1, 1);
        s1 += __shfl_xor_sync(0xffffffffu, s1, 2);
        l0 = l0 * a0 + s0; l1 = l1 * a1 + s1;
        m0 = mn0; m1 = mn1;

#pragma unroll
        for (int j = 0; j < 8; ++j) {
            cO[j][0] *= a0; cO[j][1] *= a0;
            cO[j][2] *= a1; cO[j][3] *= a1;
        }

#pragma unroll
        for (int kk = 0; kk < 4; ++kk) {
            uint32_t ah4[4] = {PH[2*kk][0], PH[2*kk][1], PH[2*kk+1][0], PH[2*kk+1][1]};
            uint32_t al4[4] = {PL[2*kk][0], PL[2*kk][1], PL[2*kk+1][0], PL[2*kk+1][1]};
            uint32_t krowoff = (uint32_t)kk * (16 * AT_STR);
#pragma unroll
            for (int nj2 = 0; nj2 < 4; ++nj2) {
                uint32_t vh4[4], vl4[4];
                LDSM4T(vh4, kb + 18432 + vtrow + krowoff + nj2 * 32);
                LDSM4T(vl4, kb + 27648 + vtrow + krowoff + nj2 * 32);
#pragma unroll
                for (int half = 0; half < 2; ++half) {
                    int j = nj2 * 2 + half;
                    uint32_t bhh[2] = {vh4[half * 2], vh4[half * 2 + 1]};
                    mma16816(cO[j], ah4, bhh);
                }
#pragma unroll
                for (int half = 0; half < 2; ++half) {
                    int j = nj2 * 2 + half;
                    uint32_t bll[2] = {vl4[half * 2], vl4[half * 2 + 1]};
                    mma16816(cO[j], ah4, bll);
                }
#pragma unroll
                for (int half = 0; half < 2; ++half) {
                    int j = nj2 * 2 + half;
                    uint32_t bhh[2] = {vh4[half * 2], vh4[half * 2 + 1]};
                    mma16816(cO[j], al4, bhh);
                }
            }
        }

        if (++s == 3) s = 0;
    }

    float inv0 = 1.0f / l0, inv1 = 1.0f / l1;
    size_t row0 = (size_t)(b * SEQ + q0 + wid * 16 + g);
    size_t row1 = row0 + 8;
#pragma unroll
    for (int j = 0; j < 8; ++j) {
        int col = h * 64 + 8 * j + 2 * q;
        uint32_t hp0, lp0, hp1, lp1;
        split2(cO[j][0] * inv0, cO[j][1] * inv0, hp0, lp0);
        split2(cO[j][2] * inv1, cO[j][3] * inv1, hp1, lp1);
        *(uint32_t*)(g_ah + row0 * D_MODEL + col) = hp0;
        *(uint32_t*)(g_al + row0 * D_MODEL + col) = lp0;
        *(uint32_t*)(g_ah + row1 * D_MODEL + col) = hp1;
        *(uint32_t*)(g_al + row1 * D_MODEL + col) = lp1;
    }
}

// ---------------- LayerNorm: hi/lo residual + NDELTA fp32 partial deltas ----
template <int NDELTA, bool F32OUT>
__global__ void ln_kernel(float* __restrict__ outf,
                          __nv_bfloat16* __restrict__ oh, __nv_bfloat16* __restrict__ ol,
                          const __nv_bfloat16* __restrict__ xh,
                          const __nv_bfloat16* __restrict__ xl,
                          const float* __restrict__ delta,
                          const float* __restrict__ g, const float* __restrict__ bta,
                          size_t in_row_stride) {
    __shared__ float red1[8];
    __shared__ float red2[8];
    int row = blockIdx.x, tid = threadIdx.x;
    int lane = tid & 31, wid = tid >> 5;
    size_t base_in = (size_t)row * in_row_stride + tid * 4;

    uint2 hp = *(const uint2*)(xh + base_in);
    uint2 lp = *(const uint2*)(xl + base_in);
    float2 h0 = bf2f2(hp.x), h1 = bf2f2(hp.y);
    float2 e0 = bf2f2(lp.x), e1 = bf2f2(lp.y);
    float4 v;
    v.x = h0.x + e0.x; v.y = h0.y + e0.y;
    v.z = h1.x + e1.x; v.w = h1.y + e1.y;
#pragma unroll
    for (int d = 0; d < NDELTA; ++d) {
        float4 dv = *(const float4*)(delta + d * DSTRIDE + (size_t)row * D_MODEL + tid * 4);
        v.x += dv.x; v.y += dv.y; v.z += dv.z; v.w += dv.w;
    }
    float s  = v.x + v.y + v.z + v.w;
    float ss = v.x * v.x + v.y * v.y + v.z * v.z + v.w * v.w;
#pragma unroll
    for (int o = 16; o > 0; o >>= 1) {
        s  += __shfl_xor_sync(0xffffffffu, s, o);
        ss += __shfl_xor_sync(0xffffffffu, ss, o);
    }
    if (lane == 0) { red1[wid] = s; red2[wid] = ss; }
    __syncthreads();
    if (tid < 32) {
        float a = (lane < 8) ? red1[lane] : 0.f;
        float b = (lane < 8) ? red2[lane] : 0.f;
#pragma unroll
        for (int o = 4; o > 0; o >>= 1) {
            a += __shfl_xor_sync(0xffffffffu, a, o);
            b += __shfl_xor_sync(0xffffffffu, b, o);
        }
        if (lane == 0) { red1[0] = a; red2[0] = b; }
    }
    __syncthreads();
    float mean = red1[0] * (1.0f / D_MODEL);
    float var  = red2[0] * (1.0f / D_MODEL) - mean * mean;
    float inv  = rsqrtf(var + 1e-5f);

    float4 g4 = *(const float4*)(g + tid * 4);
    float4 b4 = *(const float4*)(bta + tid * 4);
    float4 ov;
    ov.x = (v.x - mean) * inv * g4.x + b4.x;
    ov.y = (v.y - mean) * inv * g4.y + b4.y;
    ov.z = (v.z - mean) * inv * g4.z + b4.z;
    ov.w = (v.w - mean) * inv * g4.w + b4.w;
    size_t base = (size_t)row * D_MODEL + tid * 4;
    if (F32OUT) {
        *(float4*)(outf + base) = ov;
    } else {
        uint2 ohp, olp;
        split2(ov.x, ov.y, ohp.x, olp.x);
        split2(ov.z, ov.w, ohp.y, olp.y);
        *(uint2*)(oh + base) = ohp;
        *(uint2*)(ol + base) = olp;
    }
}

// ---------------- head ----------------
__global__ void head_kernel(float* __restrict__ out, const float* __restrict__ W,
                            const float* __restrict__ hb) {
    __shared__ float c[D_MODEL];
    int b = blockIdx.y;
    int n = blockIdx.x * 128 + threadIdx.x;
#pragma unroll
    for (int rep = 0; rep < 2; rep++) {
        int idx = rep * 128 + threadIdx.x;
        *(float4*)&c[idx * 4] = *(const float4*)(g_cls + (size_t)b * D_MODEL + idx * 4);
    }
    __syncthreads();
    const float4* W4 = (const float4*)(W + (size_t)n * D_MODEL);
    const float4* c4 = (const float4*)c;
    float acc = 0.f;
#pragma unroll 8
    for (int k = 0; k < D_MODEL / 4; k++) {
        float4 w = W4[k], cc = c4[k];
        acc += w.x * cc.x + w.y * cc.y + w.z * cc.z + w.w * cc.w;
    }
    out[(size_t)b * D_MODEL + n] = acc + hb[n];
}

// ---------------- launcher ----------------
extern "C" void kernel_launch(void* const* d_in, const int* in_sizes, int n_in,
                              void* d_out, int out_size) {
    const int*   ids  = (const int*)  d_in[0];
    const float* tok  = (const float*)d_in[1];
    const float* pos  = (const float*)d_in[2];
    const float* Wqkv = (const float*)d_in[3];
    const float* bqkv = (const float*)d_in[4];
    const float* Wo   = (const float*)d_in[5];
    const float* bo   = (const float*)d_in[6];
    const float* ln1g = (const float*)d_in[7];
    const float* ln1b = (const float*)d_in[8];
    const float* W1   = (const float*)d_in[9];
    const float* b1   = (const float*)d_in[10];
    const float* W2   = (const float*)d_in[11];
    const float* b2   = (const float*)d_in[12];
    const float* ln2g = (const float*)d_in[13];
    const float* ln2b = (const float*)d_in[14];
    const float* hg   = (const float*)d_in[15];
    const float* hbln = (const float*)d_in[16];
    const float* hW   = (const float*)d_in[17];
    const float* hb   = (const float*)d_in[18];
    float* out = (float*)d_out;

    float *ptmp, *pcls;
    __nv_bfloat16 *pwh, *pwl, *pxh, *pxl, *pah, *pal, *pfh, *pfl;
    cudaGetSymbolAddress((void**)&ptmp, g_tmp);
    cudaGetSymbolAddress((void**)&pcls, g_cls);
    cudaGetSymbolAddress((void**)&pwh,  g_wh);
    cudaGetSymbolAddress((void**)&pwl,  g_wl);
    cudaGetSymbolAddress((void**)&pxh,  g_xh);
    cudaGetSymbolAddress((void**)&pxl,  g_xl);
    cudaGetSymbolAddress((void**)&pah,  g_ah);
    cudaGetSymbolAddress((void**)&pal,  g_al);
    cudaGetSymbolAddress((void**)&pfh,  g_fh);
    cudaGetSymbolAddress((void**)&pfl,  g_fl);

    cudaFuncSetAttribute((const void*)gemm_mma<0,1,4>, cudaFuncAttributeMaxDynamicSharedMemorySize, GS_MI4);
    cudaFuncSetAttribute((const void*)gemm_mma<0,4,4>, cudaFuncAttributeMaxDynamicSharedMemorySize, GS_MI4);
    cudaFuncSetAttribute((const void*)gemm_mma<1,1,4>, cudaFuncAttributeMaxDynamicSharedMemorySize, GS_MI4);
    cudaFuncSetAttribute((const void*)gemm_mma<2,1,2>, cudaFuncAttributeMaxDynamicSharedMemorySize, GS_MI2);
    cudaFuncSetAttribute(attn_tc, cudaFuncAttributeMaxDynamicSharedMemorySize, AT_SMEM);

    embed_kernel<<<M_ROWS * D_MODEL / 1024, 256>>>(ids, tok, pos);

    const size_t N_QKV = 3145728, N_WO = 1048576, N_W1 = 4194304, N_W2 = 4194304;
    const size_t O_QKV = 0;
    const size_t O_WO  = 6 * N_QKV;
    const size_t O_W1  = O_WO + 6 * N_WO;
    const size_t O_W2  = O_W1 + 6 * N_W1;
    cvt_kernel<<<(unsigned)(6*N_QKV/16/256), 256>>>(Wqkv, pwh + O_QKV, pwl + O_QKV, (int)(6*N_QKV/16));
    cvt_kernel<<<(unsigned)(6*N_WO /16/256), 256>>>(Wo,   pwh + O_WO,  pwl + O_WO,  (int)(6*N_WO/16));
    cvt_kernel<<<(unsigned)(6*N_W1 /16/256), 256>>>(W1,   pwh + O_W1,  pwl + O_W1,  (int)(6*N_W1/16));
    cvt_kernel<<<(unsigned)(6*N_W2 /16/256), 256>>>(W2,   pwh + O_W2,  pwl + O_W2,  (int)(6*N_W2/16));

    for (int i = 0; i < NLAYER; i++) {
        size_t o_qkv = O_QKV + (size_t)i * N_QKV;
        size_t o_wo  = O_WO  + (size_t)i * N_WO;
        size_t o_w1  = O_W1  + (size_t)i * N_W1;
        size_t o_w2  = O_W2  + (size_t)i * N_W2;

        // QKV: M=128 tiles -> 1536 CTAs (10.38 -> 11 waves vs 5.19 -> 6)
        gemm_mma<2,1,2><<<dim3(3 * D_MODEL / 128, M_ROWS / 128), 256, GS_MI2>>>(
            pxh, pxl, pwh + o_qkv, pwl + o_qkv, bqkv + (size_t)i * 3 * D_MODEL,
            nullptr, nullptr, nullptr, D_MODEL, 3 * D_MODEL);

        attn_tc<<<dim3(SEQ / 128, NHEAD, BATCH), 256, AT_SMEM>>>();

        gemm_mma<0,1,4><<<dim3(D_MODEL / 128, M_ROWS / 256), 256, GS_MI4>>>(
            pah, pal, pwh + o_wo, pwl + o_wo, bo + (size_t)i * D_MODEL,
            ptmp, nullptr, nullptr, D_MODEL, D_MODEL);

        ln_kernel<1, false><<<M_ROWS, 256>>>(nullptr, pxh, pxl, pxh, pxl, ptmp,
            ln1g + (size_t)i * D_MODEL, ln1b + (size_t)i * D_MODEL, D_MODEL);

        gemm_mma<1,1,4><<<dim3(DIM_FF / 128, M_ROWS / 256), 256, GS_MI4>>>(
            pxh, pxl, pwh + o_w1, pwl + o_w1, b1 + (size_t)i * DIM_FF,
            nullptr, pfh, pfl, D_MODEL, DIM_FF);

        gemm_mma<0,4,4><<<dim3(D_MODEL / 128, M_ROWS / 256, 4), 256, GS_MI4>>>(
            pfh, pfl, pwh + o_w2, pwl + o_w2, b2 + (size_t)i * D_MODEL,
            ptmp, nullptr, nullptr, DIM_FF, D_MODEL);

        ln_kernel<4, false><<<M_ROWS, 256>>>(nullptr, pxh, pxl, pxh, pxl, ptmp,
            ln2g + (size_t)i * D_MODEL, ln2b + (size_t)i * D_MODEL, D_MODEL);
    }

    ln_kernel<0, true><<<BATCH, 256>>>(pcls, nullptr, nullptr, pxh, pxl, nullptr,
                                       hg, hbln, (size_t)SEQ * D_MODEL);
    head_kernel<<<dim3(D_MODEL / 128, BATCH), 128>>>(out, hW, hb);
}

// round 17
// speedup vs baseline: 1.1156x; 1.1156x over previous
#include <cuda_runtime.h>
#include <cuda_bf16.h>
#include <math.h>
#include <stdint.h>

#define D_MODEL 1024
#define NHEAD   16
#define DH      64
#define NLAYER  6
#define DIM_FF  4096
#define BATCH   8
#define SEQ     1024
#define M_ROWS  (BATCH*SEQ)   // 8192
#define DSTRIDE ((size_t)M_ROWS * D_MODEL)

// ---------------- scratch ----------------
__device__ float g_tmp [4 * M_ROWS * D_MODEL];
__device__ float g_cls [BATCH * D_MODEL];
__device__ unsigned char g_kpm[M_ROWS];

__device__ __nv_bfloat16 g_wh[75497472];
__device__ __nv_bfloat16 g_wl[75497472];
__device__ __nv_bfloat16 g_xh[M_ROWS * D_MODEL];
__device__ __nv_bfloat16 g_xl[M_ROWS * D_MODEL];
__device__ __nv_bfloat16 g_ah[M_ROWS * D_MODEL];
__device__ __nv_bfloat16 g_al[M_ROWS * D_MODEL];
__device__ __nv_bfloat16 g_fh[M_ROWS * DIM_FF];
__device__ __nv_bfloat16 g_fl[M_ROWS * DIM_FF];
__device__ __nv_bfloat16 g_qh[M_ROWS * D_MODEL];
__device__ __nv_bfloat16 g_ql[M_ROWS * D_MODEL];
__device__ __nv_bfloat16 g_kh[M_ROWS * D_MODEL];
__device__ __nv_bfloat16 g_kl[M_ROWS * D_MODEL];
__device__ __nv_bfloat16 g_vh[M_ROWS * D_MODEL];   // [b,h,l,dh]
__device__ __nv_bfloat16 g_vl[M_ROWS * D_MODEL];

// ---------------- helpers ----------------
__device__ __forceinline__ uint32_t smem_u32(const void* p) {
    uint32_t a;
    asm("{ .reg .u64 t; cvta.to.shared.u64 t, %1; cvt.u32.u64 %0, t; }"
        : "=r"(a) : "l"(p));
    return a;
}

#define CPA16(dst, src) \
    asm volatile("cp.async.cg.shared.global [%0], [%1], 16;" \
                 :: "r"(dst), "l"(src) : "memory")
#define CPA_COMMIT() asm volatile("cp.async.commit_group;" ::: "memory")
#define CPA_WAIT1()  asm volatile("cp.async.wait_group 1;" ::: "memory")
#define CPA_WAIT0()  asm volatile("cp.async.wait_group 0;" ::: "memory")

#define LDSM4(r, addr) \
    asm volatile("ldmatrix.sync.aligned.m8n8.x4.shared.b16 {%0,%1,%2,%3}, [%4];" \
                 : "=r"((r)[0]), "=r"((r)[1]), "=r"((r)[2]), "=r"((r)[3]) \
                 : "r"(addr))

#define LDSM4T(r, addr) \
    asm volatile("ldmatrix.sync.aligned.m8n8.x4.trans.shared.b16 {%0,%1,%2,%3}, [%4];" \
                 : "=r"((r)[0]), "=r"((r)[1]), "=r"((r)[2]), "=r"((r)[3]) \
                 : "r"(addr))

__device__ __forceinline__ void mma16816(float* d, const uint32_t* a, const uint32_t* b) {
    asm volatile(
        "mma.sync.aligned.m16n8k16.row.col.f32.bf16.bf16.f32 "
        "{%0,%1,%2,%3}, {%4,%5,%6,%7}, {%8,%9}, {%0,%1,%2,%3};"
        : "+f"(d[0]), "+f"(d[1]), "+f"(d[2]), "+f"(d[3])
        : "r"(a[0]), "r"(a[1]), "r"(a[2]), "r"(a[3]), "r"(b[0]), "r"(b[1]));
}

__device__ __forceinline__ void split2(float v0, float v1,
                                       uint32_t& hp, uint32_t& lp) {
    uint32_t u0 = __float_as_uint(v0), u1 = __float_as_uint(v1);
    asm("prmt.b32 %0, %1, %2, 0x7632;" : "=r"(hp) : "r"(u0), "r"(u1));
    float h0 = __uint_as_float(u0 & 0xffff0000u);
    float h1 = __uint_as_float(u1 & 0xffff0000u);
    float l0 = v0 - h0, l1 = v1 - h1;
    asm("cvt.rn.bf16x2.f32 %0, %1, %2;" : "=r"(lp) : "f"(l1), "f"(l0));
}

__device__ __forceinline__ float2 bf2f2(uint32_t u) {
    __nv_bfloat162 h = *(__nv_bfloat162*)&u;
    float2 r;
    r.x = __bfloat162float(h.x);
    r.y = __bfloat162float(h.y);
    return r;
}

// ---------------- embedding (+mask fused) ----------------
__global__ void embed_kernel(const int* __restrict__ ids,
                             const float* __restrict__ tok,
                             const float* __restrict__ pos) {
    int idx4 = blockIdx.x * blockDim.x + threadIdx.x;
    int base = idx4 << 2;
    int bl   = base >> 10;
    int d    = base & 1023;
    int t    = ids[bl];
    if (d == 0)
        g_kpm[bl] = (t == 0 && (bl & (SEQ - 1)) != 0) ? 1 : 0;
    float4 tv = *(const float4*)(tok + (size_t)t * D_MODEL + d);
    float4 pv = *(const float4*)(pos + (size_t)(bl & (SEQ - 1)) * D_MODEL + d);
    float4 o;
    o.x = tv.x + pv.x; o.y = tv.y + pv.y; o.z = tv.z + pv.z; o.w = tv.w + pv.w;
    uint2 hp, lp;
    split2(o.x, o.y, hp.x, lp.x);
    split2(o.z, o.w, hp.y, lp.y);
    *(uint2*)(g_xh + base) = hp;
    *(uint2*)(g_xl + base) = lp;
}

// ---------------- weight fp32 -> bf16 hi/lo (16 elems/thread) ---------------
__global__ void cvt_kernel(const float* __restrict__ s,
                           __nv_bfloat16* __restrict__ h,
                           __nv_bfloat16* __restrict__ l, int n16) {
    int i = blockIdx.x * blockDim.x + threadIdx.x;
    if (i >= n16) return;
#pragma unroll
    for (int p = 0; p < 2; ++p) {
        int j = 2 * i + p;
        float4 v0 = ((const float4*)s)[2 * j];
        float4 v1 = ((const float4*)s)[2 * j + 1];
        uint4 hv, lv;
        split2(v0.x, v0.y, hv.x, lv.x);
        split2(v0.z, v0.w, hv.y, lv.y);
        split2(v1.x, v1.y, hv.z, lv.z);
        split2(v1.z, v1.w, hv.w, lv.w);
        ((uint4*)h)[j] = hv;
        ((uint4*)l)[j] = lv;
    }
}

// ---------------- mma GEMM: C = A @ B^T + bias (R7 mainloop, 256x128) --------
// m_mult: row offset per blockIdx.y (256 normally; SEQ for last-layer CLS tiles)
#define ROWB   80
#define ATILE  (256 * ROWB)
#define BTILE  (128 * ROWB)
#define STG    (2 * ATILE + 2 * BTILE)  // 61440
#define GSMEM2 (3 * STG)                // 184320

template <int MODE, int SPLITK>
__global__ void __launch_bounds__(256, 1)
gemm_mma(const __nv_bfloat16* __restrict__ Ah, const __nv_bfloat16* __restrict__ Al,
         const __nv_bfloat16* __restrict__ Bh, const __nv_bfloat16* __restrict__ Bl,
         const float* __restrict__ bias,
         float* __restrict__ Cf,
         __nv_bfloat16* __restrict__ Ch, __nv_bfloat16* __restrict__ Cl,
         int K, int Ntot, int m_mult)
{
    extern __shared__ char sm8[];
    uint32_t sb = smem_u32(sm8);
    int tid = threadIdx.x, wid = tid >> 5, lane = tid & 31;
    int m0 = blockIdx.y * m_mult, n0 = blockIdx.x << 7;
    int kz = (SPLITK > 1) ? blockIdx.z : 0;
    int Keff = K / SPLITK;
    long kofs = (long)kz * Keff;
    int wm = wid & 3, wn = wid >> 2;
    int g = lane >> 2, q = lane & 3;

    float acc[4][8][4];
#pragma unroll
    for (int mi = 0; mi < 4; ++mi)
#pragma unroll
        for (int ni = 0; ni < 8; ++ni)
#pragma unroll
            for (int r = 0; r < 4; ++r) acc[mi][ni][r] = 0.f;

    int NC = Keff >> 5;

    auto load_stage = [&](int s, int c) {
        uint32_t st = sb + (uint32_t)s * STG;
        long kb = kofs + ((long)c << 5);
#pragma unroll
        for (int it = 0; it < 4; ++it) {
            int idx = it * 256 + tid;
            int r = idx >> 2, ch = idx & 3;
            uint32_t so = (uint32_t)r * ROWB + ch * 16;
            CPA16(st + so,         Ah + (size_t)(m0 + r) * K + kb + ch * 8);
            CPA16(st + ATILE + so, Al + (size_t)(m0 + r) * K + kb + ch * 8);
        }
#pragma unroll
        for (int it = 0; it < 2; ++it) {
            int idx = it * 256 + tid;
            int r = idx >> 2, ch = idx & 3;
            uint32_t so = (uint32_t)r * ROWB + ch * 16;
            CPA16(st + 2 * ATILE + so,         Bh + (size_t)(n0 + r) * K + kb + ch * 8);
            CPA16(st + 2 * ATILE + BTILE + so, Bl + (size_t)(n0 + r) * K + kb + ch * 8);
        }
    };

    uint32_t arow = (uint32_t)(wm * 64 + (lane & 15)) * ROWB + (lane >> 4) * 16;
    uint32_t brow = (uint32_t)(wn * 64 + ((lane >> 4) << 3) + (lane & 7)) * ROWB
                  + ((lane >> 3) & 1) * 16;

    load_stage(0, 0); CPA_COMMIT();
    load_stage(1, 1); CPA_COMMIT();

    int s = 0;
    for (int c = 0; c < NC; ++c) {
        if (c + 1 < NC) { CPA_WAIT1(); } else { CPA_WAIT0(); }
        __syncthreads();

        uint32_t base = sb + (uint32_t)s * STG;
        uint32_t aHb = base + arow, aLb = aHb + ATILE;
        uint32_t bHb = base + 2 * ATILE + brow, bLb = bHb + BTILE;

#pragma unroll
        for (int ks = 0; ks < 2; ++ks) {
            uint32_t ko = ks * 32;
            uint32_t ah[4][4], al[4][4];
#pragma unroll
            for (int mi = 0; mi < 4; ++mi) {
                LDSM4(ah[mi], aHb + mi * (16 * ROWB) + ko);
                LDSM4(al[mi], aLb + mi * (16 * ROWB) + ko);
            }
#pragma unroll
            for (int nj2 = 0; nj2 < 4; ++nj2) {
                uint32_t bh4[4], bl4[4];
                LDSM4(bh4, bHb + nj2 * (16 * ROWB) + ko);
                LDSM4(bl4, bLb + nj2 * (16 * ROWB) + ko);
#pragma unroll
                for (int half = 0; half < 2; ++half) {
                    int ni = nj2 * 2 + half;
                    uint32_t bhh[2] = {bh4[half * 2], bh4[half * 2 + 1]};
#pragma unroll
                    for (int mi = 0; mi < 4; ++mi)
                        mma16816(acc[mi][ni], ah[mi], bhh);
                }
#pragma unroll
                for (int half = 0; half < 2; ++half) {
                    int ni = nj2 * 2 + half;
                    uint32_t bll[2] = {bl4[half * 2], bl4[half * 2 + 1]};
#pragma unroll
                    for (int mi = 0; mi < 4; ++mi)
                        mma16816(acc[mi][ni], ah[mi], bll);
                }
#pragma unroll
                for (int half = 0; half < 2; ++half) {
                    int ni = nj2 * 2 + half;
                    uint32_t bhh[2] = {bh4[half * 2], bh4[half * 2 + 1]};
#pragma unroll
                    for (int mi = 0; mi < 4; ++mi)
                        mma16816(acc[mi][ni], al[mi], bhh);
                }
            }
        }

        if (c + 2 < NC) {
            int ws = s + 2; if (ws >= 3) ws -= 3;
            load_stage(ws, c + 2);
            CPA_COMMIT();
        }
        if (++s == 3) s = 0;
    }

    // ---- epilogue ----
    float* Cfz = Cf + (size_t)kz * M_ROWS * Ntot;
    float bscale = (SPLITK > 1 && kz != 0) ? 0.f : 1.f;
#pragma unroll
    for (int mi = 0; mi < 4; ++mi) {
#pragma unroll
        for (int ni = 0; ni < 8; ++ni) {
            int col = n0 + wn * 64 + ni * 8 + q * 2;
            float2 bv = *(const float2*)(bias + col);
            float* a = acc[mi][ni];
#pragma unroll
            for (int half = 0; half < 2; ++half) {
                int row = m0 + wm * 64 + mi * 16 + g + half * 8;
                float v0 = a[half * 2 + 0] + bv.x * bscale;
                float v1 = a[half * 2 + 1] + bv.y * bscale;
                if (MODE == 0) {
                    float2 o; o.x = v0; o.y = v1;
                    *(float2*)(Cfz + (size_t)row * Ntot + col) = o;
                } else if (MODE == 1) {
                    v0 = 0.5f * v0 * (1.0f + erff(v0 * 0.70710678118654752f));
                    v1 = 0.5f * v1 * (1.0f + erff(v1 * 0.70710678118654752f));
                    uint32_t hp, lp;
                    split2(v0, v1, hp, lp);
                    size_t off = (size_t)row * Ntot + col;
                    *(uint32_t*)(Ch + off) = hp;
                    *(uint32_t*)(Cl + off) = lp;
                } else {
                    int bb = row >> 10, l = row & 1023;
                    int cat = col >> 10, cc = col & 1023;
                    int hh = cc >> 6, d = cc & 63;
                    if (cat == 0) { v0 *= 0.125f; v1 *= 0.125f; }
                    uint32_t hp, lp;
                    split2(v0, v1, hp, lp);
                    size_t base2 = (((size_t)bb * NHEAD + hh) * SEQ + l) * DH + d;
                    if (cat == 0) {
                        *(uint32_t*)(g_qh + base2) = hp;
                        *(uint32_t*)(g_ql + base2) = lp;
                    } else if (cat == 1) {
                        *(uint32_t*)(g_kh + base2) = hp;
                        *(uint32_t*)(g_kl + base2) = lp;
                    } else {
                        *(uint32_t*)(g_vh + base2) = hp;
                        *(uint32_t*)(g_vl + base2) = lp;
                    }
                }
            }
        }
    }
}

// ---------------- flash attention (R13 config) -------------------------------
#define AT_STR   144
#define AT_QB    (128 * AT_STR)
#define AT_KVST  (4 * 64 * AT_STR)
#define AT_SMEM  (2 * AT_QB + 3 * AT_KVST + 3 * 64 * 4)
#define NKT      (SEQ / 64)

__global__ void __launch_bounds__(256, 1)
attn_tc() {
    extern __shared__ char sma[];
    uint32_t sb = smem_u32(sma);
    int tid = threadIdx.x, wid = tid >> 5, lane = tid & 31;
    int g = lane >> 2, q = lane & 3;
    int q0 = blockIdx.x << 7;
    int h  = blockIdx.y;
    int b  = blockIdx.z;
    size_t bh = (size_t)b * NHEAD + h;

    const __nv_bfloat16* qhp = g_qh + bh * SEQ * DH;
    const __nv_bfloat16* qlp = g_ql + bh * SEQ * DH;
    const __nv_bfloat16* khp = g_kh + bh * SEQ * DH;
    const __nv_bfloat16* klp = g_kl + bh * SEQ * DH;
    const __nv_bfloat16* vhp = g_vh + bh * SEQ * DH;
    const __nv_bfloat16* vlp = g_vl + bh * SEQ * DH;

    uint32_t sQh = sb, sQl = sb + AT_QB;
    uint32_t sKV0 = sb + 2 * AT_QB;
    float* msks = (float*)(sma + 2 * AT_QB + 3 * AT_KVST);

#pragma unroll
    for (int it = 0; it < 4; ++it) {
        int idx = it * 256 + tid;
        int r = idx >> 3, ch = idx & 7;
        uint32_t dst = (uint32_t)r * AT_STR + ch * 16;
        CPA16(sQh + dst, qhp + (size_t)(q0 + r) * DH + ch * 8);
        CPA16(sQl + dst, qlp + (size_t)(q0 + r) * DH + ch * 8);
    }

    auto load_kv = [&](int s, int t) {
        uint32_t st = sKV0 + (uint32_t)s * AT_KVST;
#pragma unroll
        for (int it = 0; it < 2; ++it) {
            int idx = it * 256 + tid;
            int r = idx >> 3, ch = idx & 7;
            uint32_t dst = (uint32_t)r * AT_STR + ch * 16;
            size_t go = (size_t)(t * 64 + r) * DH + ch * 8;
            CPA16(st + dst,         khp + go);
            CPA16(st + 9216 + dst,  klp + go);
            CPA16(st + 18432 + dst, vhp + go);
            CPA16(st + 27648 + dst, vlp + go);
        }
        if (tid < 64)
            msks[s * 64 + tid] = g_kpm[b * SEQ + t * 64 + tid] ? 0.f : 1.f;
    };

    load_kv(0, 0); CPA_COMMIT();
    load_kv(1, 1); CPA_COMMIT();

    uint32_t qrow = (uint32_t)(wid * 16 + (lane & 15)) * AT_STR + (lane >> 4) * 16;
    uint32_t brow = (uint32_t)(((lane >> 4) << 3) + (lane & 7)) * AT_STR
                  + ((lane >> 3) & 1) * 16;
    uint32_t vtrow = (uint32_t)((lane & 7) + ((lane >> 3) & 1) * 8) * AT_STR
                   + (lane >> 4) * 16;

    uint32_t qfh[4][4], qfl[4][4];
    float cO[8][4];
#pragma unroll
    for (int j = 0; j < 8; ++j)
#pragma unroll
        for (int r = 0; r < 4; ++r) cO[j][r] = 0.f;
    float m0 = -1e30f, m1 = -1e30f, l0 = 0.f, l1 = 0.f;

    int s = 0;
    for (int t = 0; t < NKT; ++t) {
        if (t + 1 < NKT) { CPA_WAIT1(); } else { CPA_WAIT0(); }
        __syncthreads();
        if (t + 2 < NKT) {
            int ws = s + 2; if (ws >= 3) ws -= 3;
            load_kv(ws, t + 2);
            CPA_COMMIT();
        }

        if (t == 0) {
#pragma unroll
            for (int ks = 0; ks < 4; ++ks) {
                LDSM4(qfh[ks], sQh + qrow + ks * 32);
                LDSM4(qfl[ks], sQl + qrow + ks * 32);
            }
        }

        uint32_t kb = sKV0 + (uint32_t)s * AT_KVST;

        float cS[8][4];
#pragma unroll
        for (int j = 0; j < 8; ++j)
#pragma unroll
            for (int r = 0; r < 4; ++r) cS[j][r] = 0.f;

#pragma unroll
        for (int ks = 0; ks < 4; ++ks) {
            uint32_t ko = ks * 32;
#pragma unroll
            for (int nj2 = 0; nj2 < 4; ++nj2) {
                uint32_t kh4[4], kl4[4];
                LDSM4(kh4, kb + brow + nj2 * (16 * AT_STR) + ko);
                LDSM4(kl4, kb + 9216 + brow + nj2 * (16 * AT_STR) + ko);
#pragma unroll
                for (int half = 0; half < 2; ++half) {
                    int j = nj2 * 2 + half;
                    uint32_t bhh[2] = {kh4[half * 2], kh4[half * 2 + 1]};
                    mma16816(cS[j], qfh[ks], bhh);
                }
#pragma unroll
                for (int half = 0; half < 2; ++half) {
                    int j = nj2 * 2 + half;
                    uint32_t bll[2] = {kl4[half * 2], kl4[half * 2 + 1]};
                    mma16816(cS[j], qfh[ks], bll);
                }
#pragma unroll
                for (int half = 0; half < 2; ++half) {
                    int j = nj2 * 2 + half;
                    uint32_t bhh[2] = {kh4[half * 2], kh4[half * 2 + 1]};
                    mma16816(cS[j], qfl[ks], bhh);
                }
            }
        }

        float lm0 = -1e30f, lm1 = -1e30f;
#pragma unroll
        for (int j = 0; j < 8; ++j) {
            lm0 = fmaxf(lm0, fmaxf(cS[j][0], cS[j][1]));
            lm1 = fmaxf(lm1, fmaxf(cS[j][2], cS[j][3]));
        }
        lm0 = fmaxf(lm0, __shfl_xor_sync(0xffffffffu, lm0, 1));
        lm0 = fmaxf(lm0, __shfl_xor_sync(0xffffffffu, lm0, 2));
        lm1 = fmaxf(lm1, __shfl_xor_sync(0xffffffffu, lm1, 1));
        lm1 = fmaxf(lm1, __shfl_xor_sync(0xffffffffu, lm1, 2));
        float mn0 = fmaxf(m0, lm0), mn1 = fmaxf(m1, lm1);
        float a0 = __expf(m0 - mn0), a1 = __expf(m1 - mn1);

        uint32_t PH[8][2], PL[8][2];
        float s0 = 0.f, s1 = 0.f;
#pragma unroll
        for (int j = 0; j < 8; ++j) {
            float mmA = msks[s * 64 + 8 * j + 2 * q];
            float mmB = msks[s * 64 + 8 * j + 2 * q + 1];
            float p0 = __expf(cS[j][0] - mn0) * mmA;
            float p1 = __expf(cS[j][1] - mn0) * mmB;
            float p2 = __expf(cS[j][2] - mn1) * mmA;
            float p3 = __expf(cS[j][3] - mn1) * mmB;
            s0 += p0 + p1; s1 += p2 + p3;
            split2(p0, p1, PH[j][0], PL[j][0]);
            split2(p2, p3, PH[j][1], PL[j][1]);
        }
        s0 += __shfl_xor_sync(0xffffffffu, s0, 1);
        s0 += __shfl_xor_sync(0xffffffffu, s0, 2);
        s1 += __shfl_xor_sync(0xffffffffu, s1, 1);
        s1 += __shfl_xor_sync(0xffffffffu, s1, 2);
        l0 = l0 * a0 + s0; l1 = l1 * a1 + s1;
        m0 = mn0; m1 = mn1;

#pragma unroll
        for (int j = 0; j < 8; ++j) {
            cO[j][0] *= a0; cO[j][1] *= a0;
            cO[j][2] *= a1; cO[j][3] *= a1;
        }

#pragma unroll
        for (int kk = 0; kk < 4; ++kk) {
            uint32_t ah4[4] = {PH[2*kk][0], PH[2*kk][1], PH[2*kk+1][0], PH[2*kk+1][1]};
            uint32_t al4[4] = {PL[2*kk][0], PL[2*kk][1], PL[2*kk+1][0], PL[2*kk+1][1]};
            uint32_t krowoff = (uint32_t)kk * (16 * AT_STR);
#pragma unroll
            for (int nj2 = 0; nj2 < 4; ++nj2) {
                uint32_t vh4[4], vl4[4];
                LDSM4T(vh4, kb + 18432 + vtrow + krowoff + nj2 * 32);
                LDSM4T(vl4, kb + 27648 + vtrow + krowoff + nj2 * 32);
#pragma unroll
                for (int half = 0; half < 2; ++half) {
                    int j = nj2 * 2 + half;
                    uint32_t bhh[2] = {vh4[half * 2], vh4[half * 2 + 1]};
                    mma16816(cO[j], ah4, bhh);
                }
#pragma unroll
                for (int half = 0; half < 2; ++half) {
                    int j = nj2 * 2 + half;
                    uint32_t bll[2] = {vl4[half * 2], vl4[half * 2 + 1]};
                    mma16816(cO[j], ah4, bll);
                }
#pragma unroll
                for (int half = 0; half < 2; ++half) {
                    int j = nj2 * 2 + half;
                    uint32_t bhh[2] = {vh4[half * 2], vh4[half * 2 + 1]};
                    mma16816(cO[j], al4, bhh);
                }
            }
        }

        if (++s == 3) s = 0;
    }

    float inv0 = 1.0f / l0, inv1 = 1.0f / l1;
    size_t row0 = (size_t)(b * SEQ + q0 + wid * 16 + g);
    size_t row1 = row0 + 8;
#pragma unroll
    for (int j = 0; j < 8; ++j) {
        int col = h * 64 + 8 * j + 2 * q;
        uint32_t hp0, lp0, hp1, lp1;
        split2(cO[j][0] * inv0, cO[j][1] * inv0, hp0, lp0);
        split2(cO[j][2] * inv1, cO[j][3] * inv1, hp1, lp1);
        *(uint32_t*)(g_ah + row0 * D_MODEL + col) = hp0;
        *(uint32_t*)(g_al + row0 * D_MODEL + col) = lp0;
        *(uint32_t*)(g_ah + row1 * D_MODEL + col) = hp1;
        *(uint32_t*)(g_al + row1 * D_MODEL + col) = lp1;
    }
}

// ---------------- LayerNorm: hi/lo residual + NDELTA fp32 partial deltas ----
// row = blockIdx.x * row_mult (row_mult=SEQ for last-layer CLS-only LNs)
template <int NDELTA, bool F32OUT>
__global__ void ln_kernel(float* __restrict__ outf,
                          __nv_bfloat16* __restrict__ oh, __nv_bfloat16* __restrict__ ol,
                          const __nv_bfloat16* __restrict__ xh,
                          const __nv_bfloat16* __restrict__ xl,
                          const float* __restrict__ delta,
                          const float* __restrict__ g, const float* __restrict__ bta,
                          size_t in_row_stride, int row_mult) {
    __shared__ float red1[8];
    __shared__ float red2[8];
    int row = blockIdx.x * row_mult, tid = threadIdx.x;
    int lane = tid & 31, wid = tid >> 5;
    size_t base_in = (size_t)blockIdx.x * in_row_stride * row_mult + tid * 4;
    // NOTE: for row_mult==1 this is blockIdx.x*in_row_stride (original semantics);
    // for row_mult==SEQ, in_row_stride is D_MODEL so base_in = row*D_MODEL.

    uint2 hp = *(const uint2*)(xh + base_in);
    uint2 lp = *(const uint2*)(xl + base_in);
    float2 h0 = bf2f2(hp.x), h1 = bf2f2(hp.y);
    float2 e0 = bf2f2(lp.x), e1 = bf2f2(lp.y);
    float4 v;
    v.x = h0.x + e0.x; v.y = h0.y + e0.y;
    v.z = h1.x + e1.x; v.w = h1.y + e1.y;
#pragma unroll
    for (int d = 0; d < NDELTA; ++d) {
        float4 dv = *(const float4*)(delta + d * DSTRIDE + (size_t)row * D_MODEL + tid * 4);
        v.x += dv.x; v.y += dv.y; v.z += dv.z; v.w += dv.w;
    }
    float s  = v.x + v.y + v.z + v.w;
    float ss = v.x * v.x + v.y * v.y + v.z * v.z + v.w * v.w;
#pragma unroll
    for (int o = 16; o > 0; o >>= 1) {
        s  += __shfl_xor_sync(0xffffffffu, s, o);
        ss += __shfl_xor_sync(0xffffffffu, ss, o);
    }
    if (lane == 0) { red1[wid] = s; red2[wid] = ss; }
    __syncthreads();
    if (tid < 32) {
        float a = (lane < 8) ? red1[lane] : 0.f;
        float b = (lane < 8) ? red2[lane] : 0.f;
#pragma unroll
        for (int o = 4; o > 0; o >>= 1) {
            a += __shfl_xor_sync(0xffffffffu, a, o);
            b += __shfl_xor_sync(0xffffffffu, b, o);
        }
        if (lane == 0) { red1[0] = a; red2[0] = b; }
    }
    __syncthreads();
    float mean = red1[0] * (1.0f / D_MODEL);
    float var  = red2[0] * (1.0f / D_MODEL) - mean * mean;
    float inv  = rsqrtf(var + 1e-5f);

    float4 g4 = *(const float4*)(g + tid * 4);
    float4 b4 = *(const float4*)(bta + tid * 4);
    float4 ov;
    ov.x = (v.x - mean) * inv * g4.x + b4.x;
    ov.y = (v.y - mean) * inv * g4.y + b4.y;
    ov.z = (v.z - mean) * inv * g4.z + b4.z;
    ov.w = (v.w - mean) * inv * g4.w + b4.w;
    size_t base;
    if (F32OUT) {
        base = (size_t)blockIdx.x * D_MODEL + tid * 4;   // compact output (cls)
        *(float4*)(outf + base) = ov;
    } else {
        base = (size_t)row * D_MODEL + tid * 4;
        uint2 ohp, olp;
        split2(ov.x, ov.y, ohp.x, olp.x);
        split2(ov.z, ov.w, ohp.y, olp.y);
        *(uint2*)(oh + base) = ohp;
        *(uint2*)(ol + base) = olp;
    }
}

// ---------------- head ----------------
__global__ void head_kernel(float* __restrict__ out, const float* __restrict__ W,
                            const float* __restrict__ hb) {
    __shared__ float c[D_MODEL];
    int b = blockIdx.y;
    int n = blockIdx.x * 128 + threadIdx.x;
#pragma unroll
    for (int rep = 0; rep < 2; rep++) {
        int idx = rep * 128 + threadIdx.x;
        *(float4*)&c[idx * 4] = *(const float4*)(g_cls + (size_t)b * D_MODEL + idx * 4);
    }
    __syncthreads();
    const float4* W4 = (const float4*)(W + (size_t)n * D_MODEL);
    const float4* c4 = (const float4*)c;
    float acc = 0.f;
#pragma unroll 8
    for (int k = 0; k < D_MODEL / 4; k++) {
        float4 w = W4[k], cc = c4[k];
        acc += w.x * cc.x + w.y * cc.y + w.z * cc.z + w.w * cc.w;
    }
    out[(size_t)b * D_MODEL + n] = acc + hb[n];
}

// ---------------- launcher ----------------
extern "C" void kernel_launch(void* const* d_in, const int* in_sizes, int n_in,
                              void* d_out, int out_size) {
    const int*   ids  = (const int*)  d_in[0];
    const float* tok  = (const float*)d_in[1];
    const float* pos  = (const float*)d_in[2];
    const float* Wqkv = (const float*)d_in[3];
    const float* bqkv = (const float*)d_in[4];
    const float* Wo   = (const float*)d_in[5];
    const float* bo   = (const float*)d_in[6];
    const float* ln1g = (const float*)d_in[7];
    const float* ln1b = (const float*)d_in[8];
    const float* W1   = (const float*)d_in[9];
    const float* b1   = (const float*)d_in[10];
    const float* W2   = (const float*)d_in[11];
    const float* b2   = (const float*)d_in[12];
    const float* ln2g = (const float*)d_in[13];
    const float* ln2b = (const float*)d_in[14];
    const float* hg   = (const float*)d_in[15];
    const float* hbln = (const float*)d_in[16];
    const float* hW   = (const float*)d_in[17];
    const float* hb   = (const float*)d_in[18];
    float* out = (float*)d_out;

    float *ptmp, *pcls;
    __nv_bfloat16 *pwh, *pwl, *pxh, *pxl, *pah, *pal, *pfh, *pfl;
    cudaGetSymbolAddress((void**)&ptmp, g_tmp);
    cudaGetSymbolAddress((void**)&pcls, g_cls);
    cudaGetSymbolAddress((void**)&pwh,  g_wh);
    cudaGetSymbolAddress((void**)&pwl,  g_wl);
    cudaGetSymbolAddress((void**)&pxh,  g_xh);
    cudaGetSymbolAddress((void**)&pxl,  g_xl);
    cudaGetSymbolAddress((void**)&pah,  g_ah);
    cudaGetSymbolAddress((void**)&pal,  g_al);
    cudaGetSymbolAddress((void**)&pfh,  g_fh);
    cudaGetSymbolAddress((void**)&pfl,  g_fl);

    cudaFuncSetAttribute((const void*)gemm_mma<0,1>, cudaFuncAttributeMaxDynamicSharedMemorySize, GSMEM2);
    cudaFuncSetAttribute((const void*)gemm_mma<0,4>, cudaFuncAttributeMaxDynamicSharedMemorySize, GSMEM2);
    cudaFuncSetAttribute((const void*)gemm_mma<1,1>, cudaFuncAttributeMaxDynamicSharedMemorySize, GSMEM2);
    cudaFuncSetAttribute((const void*)gemm_mma<2,1>, cudaFuncAttributeMaxDynamicSharedMemorySize, GSMEM2);
    cudaFuncSetAttribute(attn_tc, cudaFuncAttributeMaxDynamicSharedMemorySize, AT_SMEM);

    embed_kernel<<<M_ROWS * D_MODEL / 1024, 256>>>(ids, tok, pos);

    const size_t N_QKV = 3145728, N_WO = 1048576, N_W1 = 4194304, N_W2 = 4194304;
    const size_t O_QKV = 0;
    const size_t O_WO  = 6 * N_QKV;
    const size_t O_W1  = O_WO + 6 * N_WO;
    const size_t O_W2  = O_W1 + 6 * N_W1;
    cvt_kernel<<<(unsigned)(6*N_QKV/16/256), 256>>>(Wqkv, pwh + O_QKV, pwl + O_QKV, (int)(6*N_QKV/16));
    cvt_kernel<<<(unsigned)(6*N_WO /16/256), 256>>>(Wo,   pwh + O_WO,  pwl + O_WO,  (int)(6*N_WO/16));
    cvt_kernel<<<(unsigned)(6*N_W1 /16/256), 256>>>(W1,   pwh + O_W1,  pwl + O_W1,  (int)(6*N_W1/16));
    cvt_kernel<<<(unsigned)(6*N_W2 /16/256), 256>>>(W2,   pwh + O_W2,  pwl + O_W2,  (int)(6*N_W2/16));

    for (int i = 0; i < NLAYER; i++) {
        size_t o_qkv = O_QKV + (size_t)i * N_QKV;
        size_t o_wo  = O_WO  + (size_t)i * N_WO;
        size_t o_w1  = O_W1  + (size_t)i * N_W1;
        size_t o_w2  = O_W2  + (size_t)i * N_W2;
        bool last = (i == NLAYER - 1);

        // QKV always full (K and V span all positions)
        gemm_mma<2,1><<<dim3(3 * D_MODEL / 128, M_ROWS / 256), 256, GSMEM2>>>(
            pxh, pxl, pwh + o_qkv, pwl + o_qkv, bqkv + (size_t)i * 3 * D_MODEL,
            nullptr, nullptr, nullptr, D_MODEL, 3 * D_MODEL, 256);

        // last layer: only query tile 0 feeds the CLS row
        attn_tc<<<dim3(last ? 1 : SEQ / 128, NHEAD, BATCH), 256, AT_SMEM>>>();

        if (!last) {
            gemm_mma<0,1><<<dim3(D_MODEL / 128, M_ROWS / 256), 256, GSMEM2>>>(
                pah, pal, pwh + o_wo, pwl + o_wo, bo + (size_t)i * D_MODEL,
                ptmp, nullptr, nullptr, D_MODEL, D_MODEL, 256);

            ln_kernel<1, false><<<M_ROWS, 256>>>(nullptr, pxh, pxl, pxh, pxl, ptmp,
                ln1g + (size_t)i * D_MODEL, ln1b + (size_t)i * D_MODEL, D_MODEL, 1);

            gemm_mma<1,1><<<dim3(DIM_FF / 128, M_ROWS / 256), 256, GSMEM2>>>(
                pxh, pxl, pwh + o_w1, pwl + o_w1, b1 + (size_t)i * DIM_FF,
                nullptr, pfh, pfl, D_MODEL, DIM_FF, 256);

            gemm_mma<0,4><<<dim3(D_MODEL / 128, M_ROWS / 256, 4), 256, GSMEM2>>>(
                pfh, pfl, pwh + o_w2, pwl + o_w2, b2 + (size_t)i * D_MODEL,
                ptmp, nullptr, nullptr, DIM_FF, D_MODEL, 256);

            ln_kernel<4, false><<<M_ROWS, 256>>>(nullptr, pxh, pxl, pxh, pxl, ptmp,
                ln2g + (size_t)i * D_MODEL, ln2b + (size_t)i * D_MODEL, D_MODEL, 1);
        } else {
            // CLS-only tail: tiles anchored at rows b*SEQ (one per batch)
            gemm_mma<0,1><<<dim3(D_MODEL / 128, BATCH), 256, GSMEM2>>>(
                pah, pal, pwh + o_wo, pwl + o_wo, bo + (size_t)i * D_MODEL,
                ptmp, nullptr, nullptr, D_MODEL, D_MODEL, SEQ);

            ln_kernel<1, false><<<BATCH, 256>>>(nullptr, pxh, pxl, pxh, pxl, ptmp,
                ln1g + (size_t)i * D_MODEL, ln1b + (size_t)i * D_MODEL, D_MODEL, SEQ);

            gemm_mma<1,1><<<dim3(DIM_FF / 128, BATCH), 256, GSMEM2>>>(
                pxh, pxl, pwh + o_w1, pwl + o_w1, b1 + (size_t)i * DIM_FF,
                nullptr, pfh, pfl, D_MODEL, DIM_FF, SEQ);

            gemm_mma<0,4><<<dim3(D_MODEL / 128, BATCH, 4), 256, GSMEM2>>>(
                pfh, pfl, pwh + o_w2, pwl + o_w2, b2 + (size_t)i * D_MODEL,
                ptmp, nullptr, nullptr, DIM_FF, D_MODEL, SEQ);

            ln_kernel<4, false><<<BATCH, 256>>>(nullptr, pxh, pxl, pxh, pxl, ptmp,
                ln2g + (size_t)i * D_MODEL, ln2b + (size_t)i * D_MODEL, D_MODEL, SEQ);
        }
    }

    // cls = ln(x[:,0,:]) from hi/lo rows at stride SEQ*D_MODEL; fp32 compact out
    ln_kernel<0, true><<<BATCH, 256>>>(pcls, nullptr, nullptr, pxh, pxl, nullptr,
                                       hg, hbln, (size_t)SEQ * D_MODEL, 1);
    head_kernel<<<dim3(D_MODEL / 128, BATCH), 128>>>(out, hW, hb);
}